// round 1
// baseline (speedup 1.0000x reference)
#include <cuda_runtime.h>
#include <cstdint>
#include <math.h>

// ---------------- problem constants ----------------
#define BB 16
#define TT 256
#define VV 18000
#define NSLOT 30
#define LL 10
#define GG 3
#define HH 400
#define NN (NSLOT*BB)     // 480 rows (slot-major: n = s*B + b)
#define MM (LL*NN)        // 4800 output rows (m = n*L + l)
#define H3 (3*HH)         // 1200

static const size_t POINTS_ELEMS = (size_t)MM * VV;   // 86,400,000

// ---------------- scratch (__device__ globals: allocation-free) ----------------
__device__ __align__(128) float g_dec_in[LL*NN*HH];   // decoder inputs, (l*N+n, h)
__device__ __align__(128) float g_gi[LL*NN*H3];       // input-side GRU gates (precomputed)
__device__ __align__(128) float g_h[LL*NN*HH];        // h_new per step
__device__ __align__(128) float g_hprev[NN*HH];       // running hidden
__device__ __align__(128) float g_gh[NN*H3];          // hidden-side gates for current step
__device__ __align__(128) float g_prob[LL*NN*TT];     // attention probs
__device__ __align__(128) float g_ctx[LL*NN*HH];      // attention contexts
__device__ __align__(128) float g_switch[LL*NN];      // pointer-gen switch
__device__ __align__(128) float g_Abig[MM*HH];        // h rearranged to output-row order

// ---------------- small helpers ----------------
__device__ __forceinline__ float warpMax(float v){
    #pragma unroll
    for (int o = 16; o; o >>= 1) v = fmaxf(v, __shfl_xor_sync(0xffffffffu, v, o));
    return v;
}
__device__ __forceinline__ float warpSum(float v){
    #pragma unroll
    for (int o = 16; o; o >>= 1) v += __shfl_xor_sync(0xffffffffu, v, o);
    return v;
}
__device__ __forceinline__ float sigmoidf(float x){ return 1.f / (1.f + expf(-x)); }

// ---------------- K1: gather decoder inputs ----------------
__global__ void k_decin(const float* __restrict__ emb, const float* __restrict__ slot_emb,
                        const int* __restrict__ dom, const int* __restrict__ slo,
                        const int* __restrict__ tgt){
    int idx = blockIdx.x * blockDim.x + threadIdx.x;
    if (idx >= LL*NN*HH) return;
    int h = idx % HH; int r = idx / HH; int n = r % NN; int l = r / NN;
    int s = n / BB, b = n % BB;
    float v;
    if (l == 0) v = slot_emb[dom[s]*HH + h] + slot_emb[slo[s]*HH + h];
    else {
        int tok = tgt[(b*NSLOT + s)*LL + (l-1)];
        v = emb[(size_t)tok*HH + h];
    }
    g_dec_in[idx] = v;
}

// ---------------- K2: init hidden ----------------
__global__ void k_hinit(const float* __restrict__ enc_hidden){
    int idx = blockIdx.x * blockDim.x + threadIdx.x;
    if (idx >= NN*HH) return;
    int n = idx / HH, h = idx % HH;
    g_hprev[idx] = enc_hidden[(n % BB)*HH + h];
}

// ---------------- generic SGEMM: C[m*ldc+n] = sum_k A[m*K+k]*Bmat[n*K+k] (+bias) -----
// 128x128 tile, BK=16, 256 threads, 8x8 per thread (split 4+4 fragments)
template<bool BIAS>
__global__ __launch_bounds__(256) void sgemm128(
    const float* __restrict__ A, const float* __restrict__ Bm,
    const float* __restrict__ bias, float* __restrict__ C,
    int M, int Nn, int K, int ldc)
{
    __shared__ float As[16][128];
    __shared__ float Bs[16][128];
    int tid = threadIdx.x;
    int tx = tid & 15, ty = tid >> 4;
    int bm = blockIdx.y * 128, bn = blockIdx.x * 128;
    int ra = ty * 4, ca = tx * 4;
    float acc[8][8];
    #pragma unroll
    for (int i = 0; i < 8; i++)
        #pragma unroll
        for (int j = 0; j < 8; j++) acc[i][j] = 0.f;

    for (int k0 = 0; k0 < K; k0 += 16){
        #pragma unroll
        for (int i = tid; i < 512; i += 256){
            int r = i >> 2, c4 = i & 3;
            int gm = bm + r;
            float4 v = make_float4(0,0,0,0);
            if (gm < M) v = *(const float4*)(A + (size_t)gm*K + k0 + c4*4);
            As[c4*4+0][r] = v.x; As[c4*4+1][r] = v.y; As[c4*4+2][r] = v.z; As[c4*4+3][r] = v.w;
        }
        #pragma unroll
        for (int i = tid; i < 512; i += 256){
            int r = i >> 2, c4 = i & 3;
            int gn = bn + r;
            float4 v = make_float4(0,0,0,0);
            if (gn < Nn) v = *(const float4*)(Bm + (size_t)gn*K + k0 + c4*4);
            Bs[c4*4+0][r] = v.x; Bs[c4*4+1][r] = v.y; Bs[c4*4+2][r] = v.z; Bs[c4*4+3][r] = v.w;
        }
        __syncthreads();
        #pragma unroll
        for (int k = 0; k < 16; k++){
            float a[8], b[8];
            *(float4*)&a[0] = *(const float4*)&As[k][ra];
            *(float4*)&a[4] = *(const float4*)&As[k][ra + 64];
            *(float4*)&b[0] = *(const float4*)&Bs[k][ca];
            *(float4*)&b[4] = *(const float4*)&Bs[k][ca + 64];
            #pragma unroll
            for (int i = 0; i < 8; i++)
                #pragma unroll
                for (int j = 0; j < 8; j++) acc[i][j] += a[i]*b[j];
        }
        __syncthreads();
    }
    #pragma unroll
    for (int i = 0; i < 8; i++){
        int gm = bm + ((i < 4) ? (ra + i) : (64 + ra + i - 4));
        if (gm >= M) continue;
        #pragma unroll
        for (int j = 0; j < 8; j++){
            int gn = bn + ((j < 4) ? (ca + j) : (64 + ca + j - 4));
            if (gn < Nn){
                float v = acc[i][j];
                if (BIAS) v += bias[gn];
                C[(size_t)gm*ldc + gn] = v;
            }
        }
    }
}

// 64x64 tile version for the small sequential GRU GEMMs
template<bool BIAS>
__global__ __launch_bounds__(256) void sgemm64(
    const float* __restrict__ A, const float* __restrict__ Bm,
    const float* __restrict__ bias, float* __restrict__ C,
    int M, int Nn, int K, int ldc)
{
    __shared__ float As[16][64];
    __shared__ float Bs[16][64];
    int tid = threadIdx.x;
    int tx = tid & 15, ty = tid >> 4;
    int bm = blockIdx.y * 64, bn = blockIdx.x * 64;
    float acc[4][4];
    #pragma unroll
    for (int i = 0; i < 4; i++)
        #pragma unroll
        for (int j = 0; j < 4; j++) acc[i][j] = 0.f;

    for (int k0 = 0; k0 < K; k0 += 16){
        {
            int r = tid >> 2, c4 = tid & 3;
            int gm = bm + r;
            float4 v = make_float4(0,0,0,0);
            if (gm < M) v = *(const float4*)(A + (size_t)gm*K + k0 + c4*4);
            As[c4*4+0][r] = v.x; As[c4*4+1][r] = v.y; As[c4*4+2][r] = v.z; As[c4*4+3][r] = v.w;
            int gn = bn + r;
            float4 w = make_float4(0,0,0,0);
            if (gn < Nn) w = *(const float4*)(Bm + (size_t)gn*K + k0 + c4*4);
            Bs[c4*4+0][r] = w.x; Bs[c4*4+1][r] = w.y; Bs[c4*4+2][r] = w.z; Bs[c4*4+3][r] = w.w;
        }
        __syncthreads();
        #pragma unroll
        for (int k = 0; k < 16; k++){
            float a[4], b[4];
            *(float4*)&a[0] = *(const float4*)&As[k][ty*4];
            *(float4*)&b[0] = *(const float4*)&Bs[k][tx*4];
            #pragma unroll
            for (int i = 0; i < 4; i++)
                #pragma unroll
                for (int j = 0; j < 4; j++) acc[i][j] += a[i]*b[j];
        }
        __syncthreads();
    }
    #pragma unroll
    for (int i = 0; i < 4; i++){
        int gm = bm + ty*4 + i;
        if (gm >= M) continue;
        #pragma unroll
        for (int j = 0; j < 4; j++){
            int gn = bn + tx*4 + j;
            if (gn < Nn){
                float v = acc[i][j];
                if (BIAS) v += bias[gn];
                C[(size_t)gm*ldc + gn] = v;
            }
        }
    }
}

// ---------------- K3: GRU gate fuse for step l ----------------
__global__ void k_gate(int l){
    int idx = blockIdx.x * blockDim.x + threadIdx.x;
    if (idx >= NN*HH) return;
    int n = idx / HH, k = idx % HH;
    const float* gi = g_gi + (size_t)(l*NN + n)*H3;
    const float* gh = g_gh + (size_t)n*H3;
    float r  = sigmoidf(gi[k]        + gh[k]);
    float z  = sigmoidf(gi[HH + k]   + gh[HH + k]);
    float nn = tanhf   (gi[2*HH + k] + r * gh[2*HH + k]);
    float hp = g_hprev[idx];
    float hn = (1.f - z) * nn + z * hp;
    g_h[(size_t)(l*NN + n)*HH + k] = hn;
    g_hprev[idx] = hn;
}

// ---------------- K4: attention (scores -> softmax -> context) ----------------
// grid = L*B blocks, 256 threads. Each block handles all NS=30 slots of one (l, batch).
#define ENC_PAD 68
__global__ __launch_bounds__(256) void k_attn(const float* __restrict__ enc_out,
                                              const int* __restrict__ lens){
    extern __shared__ float sm[];
    float* sh_h   = sm;                         // NS*HH   = 12000
    float* sh_enc = sm + NSLOT*HH;              // TT*68   = 17408
    float* sh_sc  = sh_enc + TT*ENC_PAD;        // NS*TT   = 7680
    __shared__ float red[8];
    __shared__ float s_mx, s_sum;

    int l  = blockIdx.x / BB;
    int bb = blockIdx.x % BB;
    int tid = threadIdx.x;
    int lane = tid & 31, wrp = tid >> 5;
    int t = tid;   // blockDim == TT

    for (int i = tid; i < NSLOT*HH; i += 256){
        int s = i / HH, h = i % HH;
        sh_h[i] = g_h[(size_t)(l*NN + s*BB + bb)*HH + h];
    }
    for (int i = tid; i < NSLOT*TT; i += 256) sh_sc[i] = 0.f;
    __syncthreads();

    // scores: sh_sc[s][t] = dot(h_s, enc[bb, t, :])
    for (int kc = 0; kc < HH; kc += 64){
        int kw = min(64, HH - kc);
        for (int i = tid; i < TT*kw; i += 256){
            int tt2 = i / kw, kk = i % kw;
            sh_enc[tt2*ENC_PAD + kk] = enc_out[((size_t)bb*TT + tt2)*HH + kc + kk];
        }
        __syncthreads();
        for (int sg = 0; sg < NSLOT; sg += 10){
            float acc[10];
            #pragma unroll
            for (int u = 0; u < 10; u++) acc[u] = 0.f;
            for (int kk = 0; kk < kw; kk += 4){
                float4 e = *(const float4*)&sh_enc[t*ENC_PAD + kk];
                #pragma unroll
                for (int u = 0; u < 10; u++){
                    float4 hv = *(const float4*)&sh_h[(sg+u)*HH + kc + kk];
                    acc[u] += hv.x*e.x + hv.y*e.y + hv.z*e.z + hv.w*e.w;
                }
            }
            #pragma unroll
            for (int u = 0; u < 10; u++) sh_sc[(sg+u)*TT + t] += acc[u];
        }
        __syncthreads();
    }

    int len = lens[bb];
    // masked softmax over t, per slot
    for (int s = 0; s < NSLOT; s++){
        float v = (t < len) ? sh_sc[s*TT + t] : -1e9f;
        float m = warpMax(v);
        if (lane == 0) red[wrp] = m;
        __syncthreads();
        if (tid == 0){
            float mm = red[0];
            #pragma unroll
            for (int i = 1; i < 8; i++) mm = fmaxf(mm, red[i]);
            s_mx = mm;
        }
        __syncthreads();
        float p = expf(v - s_mx);
        float su = warpSum(p);
        if (lane == 0) red[wrp] = su;
        __syncthreads();
        if (tid == 0){
            float ss = 0.f;
            #pragma unroll
            for (int i = 0; i < 8; i++) ss += red[i];
            s_sum = ss;
        }
        __syncthreads();
        p /= s_sum;
        sh_sc[s*TT + t] = p;
        g_prob[(size_t)(l*NN + s*BB + bb)*TT + t] = p;
        __syncthreads();
    }

    // context: ctx[s][h] = sum_t prob[s][t]*enc[bb, t, h]
    for (int hc = 0; hc < HH; hc += 64){
        int hw = min(64, HH - hc);
        __syncthreads();
        for (int i = tid; i < TT*hw; i += 256){
            int tt2 = i / hw, hh = i % hw;
            sh_enc[tt2*ENC_PAD + hh] = enc_out[((size_t)bb*TT + tt2)*HH + hc + hh];
        }
        __syncthreads();
        int nq = NSLOT * (hw >> 2);
        for (int oi = tid; oi < nq; oi += 256){
            int s  = oi / (hw >> 2);
            int h4 = (oi % (hw >> 2)) * 4;
            float4 a = make_float4(0,0,0,0);
            for (int tt2 = 0; tt2 < TT; tt2++){
                float p = sh_sc[s*TT + tt2];
                float4 e = *(const float4*)&sh_enc[tt2*ENC_PAD + h4];
                a.x += p*e.x; a.y += p*e.y; a.z += p*e.z; a.w += p*e.w;
            }
            *(float4*)&g_ctx[(size_t)(l*NN + s*BB + bb)*HH + hc + h4] = a;
        }
    }
}

// ---------------- K5: pointer-gen switch ----------------
__global__ void k_switch(const float* __restrict__ w_ratio, const float* __restrict__ b_ratio){
    int row = blockIdx.x;         // l*N + n
    int tid = threadIdx.x;        // 128
    const float* h = g_h      + (size_t)row*HH;
    const float* c = g_ctx    + (size_t)row*HH;
    const float* x = g_dec_in + (size_t)row*HH;
    float a = 0.f;
    for (int i = tid; i < HH; i += 128)
        a += h[i]*w_ratio[i] + c[i]*w_ratio[HH + i] + x[i]*w_ratio[2*HH + i];
    __shared__ float red[4];
    a = warpSum(a);
    if ((tid & 31) == 0) red[tid >> 5] = a;
    __syncthreads();
    if (tid == 0){
        float tot = red[0] + red[1] + red[2] + red[3] + b_ratio[0];
        g_switch[row] = sigmoidf(tot);
    }
}

// ---------------- K6: gates head (from step-0 contexts) ----------------
__global__ void k_gates(const float* __restrict__ w_gate, const float* __restrict__ b_gate,
                        float* __restrict__ out_gates){
    int n = blockIdx.x;
    int tid = threadIdx.x;        // 128
    const float* c = g_ctx + (size_t)n*HH;   // row l=0 is rows [0, N)
    float a0 = 0.f, a1 = 0.f, a2 = 0.f;
    for (int i = tid; i < HH; i += 128){
        float cv = c[i];
        a0 += cv * w_gate[i];
        a1 += cv * w_gate[HH + i];
        a2 += cv * w_gate[2*HH + i];
    }
    __shared__ float red[3][4];
    a0 = warpSum(a0); a1 = warpSum(a1); a2 = warpSum(a2);
    if ((tid & 31) == 0){
        int w = tid >> 5;
        red[0][w] = a0; red[1][w] = a1; red[2][w] = a2;
    }
    __syncthreads();
    if (tid < GG){
        float tot = red[tid][0] + red[tid][1] + red[tid][2] + red[tid][3] + b_gate[tid];
        out_gates[(size_t)n*GG + tid] = tot;
    }
}

// ---------------- K7: rearrange h into output-row order ----------------
__global__ void k_rearr(){
    int idx = blockIdx.x * blockDim.x + threadIdx.x;
    if (idx >= MM*HH) return;
    int h = idx % HH; int m = idx / HH;
    int n = m / LL, l = m % LL;
    g_Abig[idx] = g_h[(size_t)(l*NN + n)*HH + h];
}

// ---------------- K8: softmax + pointer scatter + mix (in place on logits) --------
__global__ __launch_bounds__(256) void k_softmix(float* __restrict__ out,
                                                 const int* __restrict__ story){
    extern __shared__ float pctx[];           // VV floats
    __shared__ float red[8];
    __shared__ float s_mx, s_sum;
    int m = blockIdx.x, tid = threadIdx.x;
    int lane = tid & 31, wrp = tid >> 5;
    int n = m / LL, l = m % LL, bb = n % BB;
    int rowa = l*NN + n;
    float sw = g_switch[rowa];

    for (int i = tid; i < VV; i += 256) pctx[i] = 0.f;
    __syncthreads();
    {
        float p = g_prob[(size_t)rowa*TT + tid];  // blockDim == TT
        int c = story[bb*TT + tid];
        atomicAdd(&pctx[c], p);
    }
    __syncthreads();

    float* base = out + (size_t)m*VV;
    float lm = -INFINITY;
    for (int v = tid; v < VV; v += 256) lm = fmaxf(lm, base[v]);
    lm = warpMax(lm);
    if (lane == 0) red[wrp] = lm;
    __syncthreads();
    if (tid == 0){
        float mm = red[0];
        #pragma unroll
        for (int i = 1; i < 8; i++) mm = fmaxf(mm, red[i]);
        s_mx = mm;
    }
    __syncthreads();
    float mx = s_mx;
    float ls = 0.f;
    for (int v = tid; v < VV; v += 256) ls += expf(base[v] - mx);
    ls = warpSum(ls);
    if (lane == 0) red[wrp] = ls;
    __syncthreads();
    if (tid == 0){
        float ss = 0.f;
        #pragma unroll
        for (int i = 0; i < 8; i++) ss += red[i];
        s_sum = ss;
    }
    __syncthreads();
    float scale = sw / s_sum;
    float osw = 1.f - sw;
    for (int v = tid; v < VV; v += 256)
        base[v] = expf(base[v] - mx) * scale + osw * pctx[v];
}

// ---------------- launch ----------------
extern "C" void kernel_launch(void* const* d_in, const int* in_sizes, int n_in,
                              void* d_out, int out_size){
    const float* enc_hidden = (const float*)d_in[0];
    const float* enc_out    = (const float*)d_in[1];
    const float* emb        = (const float*)d_in[2];
    const float* w_ih       = (const float*)d_in[3];
    const float* w_hh       = (const float*)d_in[4];
    const float* b_ih       = (const float*)d_in[5];
    const float* b_hh       = (const float*)d_in[6];
    const float* w_ratio    = (const float*)d_in[7];
    const float* b_ratio    = (const float*)d_in[8];
    const float* w_gate     = (const float*)d_in[9];
    const float* b_gate     = (const float*)d_in[10];
    const float* slot_emb   = (const float*)d_in[11];
    const int*   lens       = (const int*)d_in[12];
    const int*   story      = (const int*)d_in[13];
    const int*   tgt        = (const int*)d_in[14];
    const int*   dom        = (const int*)d_in[15];
    const int*   slo        = (const int*)d_in[16];
    float* out = (float*)d_out;

    float *p_dec, *p_gi, *p_hprev, *p_gh, *p_Abig;
    cudaGetSymbolAddress((void**)&p_dec,   g_dec_in);
    cudaGetSymbolAddress((void**)&p_gi,    g_gi);
    cudaGetSymbolAddress((void**)&p_hprev, g_hprev);
    cudaGetSymbolAddress((void**)&p_gh,    g_gh);
    cudaGetSymbolAddress((void**)&p_Abig,  g_Abig);

    const int ATTN_SMEM = (NSLOT*HH + TT*ENC_PAD + NSLOT*TT) * 4;  // 148352 B
    cudaFuncSetAttribute(k_attn, cudaFuncAttributeMaxDynamicSharedMemorySize, ATTN_SMEM);
    cudaFuncSetAttribute(k_softmix, cudaFuncAttributeMaxDynamicSharedMemorySize, VV*4);

    // 1) decoder inputs + h0
    k_decin<<<(LL*NN*HH + 255)/256, 256>>>(emb, slot_emb, dom, slo, tgt);
    k_hinit<<<(NN*HH + 255)/256, 256>>>(enc_hidden);

    // 2) input-side gates for ALL steps in one GEMM: (4800 x 1200 x 400) + b_ih
    {
        dim3 grid((H3 + 127)/128, (MM + 127)/128);
        sgemm128<true><<<grid, 256>>>(p_dec, w_ih, b_ih, p_gi, MM, H3, HH, H3);
    }

    // 3) GRU recurrence: 10 sequential (gh GEMM + gate fuse)
    for (int l = 0; l < LL; l++){
        dim3 grid((H3 + 63)/64, (NN + 63)/64);
        sgemm64<true><<<grid, 256>>>(p_hprev, w_hh, b_hh, p_gh, NN, H3, HH, H3);
        k_gate<<<(NN*HH + 255)/256, 256>>>(l);
    }

    // 4) attention for all (l, batch)
    k_attn<<<LL*BB, 256, ATTN_SMEM>>>(enc_out, lens);

    // 5) switch per (l, n); 6) gates head from step-0 contexts
    k_switch<<<LL*NN, 128>>>(w_ratio, b_ratio);
    k_gates<<<NN, 128>>>(w_gate, b_gate, out + POINTS_ELEMS);

    // 7) big vocab GEMM: logits straight into d_out in final row order
    k_rearr<<<(MM*HH + 255)/256, 256>>>();
    {
        dim3 grid((VV + 127)/128, (MM + 127)/128);
        sgemm128<false><<<grid, 256>>>(p_Abig, emb, nullptr, out, MM, VV, HH, VV);
    }

    // 8) softmax + pointer scatter + mix, in place
    k_softmix<<<MM, 256, VV*4>>>(out, story);
}

// round 3
// speedup vs baseline: 1.4200x; 1.4200x over previous
#include <cuda_runtime.h>
#include <cstdint>
#include <math.h>

// ---------------- problem constants ----------------
#define BB 16
#define TT 256
#define VV 18000
#define NSLOT 30
#define LL 10
#define GG 3
#define HH 400
#define NN (NSLOT*BB)     // 480
#define MM (LL*NN)        // 4800
#define H3 (3*HH)         // 1200

static const size_t POINTS_ELEMS = (size_t)MM * VV;

// ---------------- scratch ----------------
__device__ __align__(128) float g_dec_in[LL*NN*HH];
__device__ __align__(128) float g_gi[LL*NN*H3];
__device__ __align__(128) float g_h[LL*NN*HH];
__device__ __align__(128) float g_hprev[NN*HH];
__device__ __align__(128) float g_gh[NN*H3];
__device__ __align__(128) float g_prob[LL*NN*TT];
__device__ __align__(128) float g_ctx[LL*NN*HH];
__device__ __align__(128) float g_switch[LL*NN];
__device__ __align__(128) float g_Abig[MM*HH];   // h in output-row order

// ---------------- helpers ----------------
__device__ __forceinline__ float warpMax(float v){
    #pragma unroll
    for (int o = 16; o; o >>= 1) v = fmaxf(v, __shfl_xor_sync(0xffffffffu, v, o));
    return v;
}
__device__ __forceinline__ float warpSum(float v){
    #pragma unroll
    for (int o = 16; o; o >>= 1) v += __shfl_xor_sync(0xffffffffu, v, o);
    return v;
}
__device__ __forceinline__ float sigmoidf(float x){ return 1.f / (1.f + expf(-x)); }
__device__ __forceinline__ uint32_t f2tf32(float x){
    uint32_t r;
    asm("cvt.rna.tf32.f32 %0, %1;" : "=r"(r) : "f"(x));
    return r;
}
__device__ __forceinline__ void mma_tf32(float* d, const uint32_t* a, const uint32_t* b){
    asm volatile(
        "mma.sync.aligned.m16n8k8.row.col.f32.tf32.tf32.f32 "
        "{%0,%1,%2,%3}, {%4,%5,%6,%7}, {%8,%9}, {%0,%1,%2,%3};\n"
        : "+f"(d[0]), "+f"(d[1]), "+f"(d[2]), "+f"(d[3])
        : "r"(a[0]), "r"(a[1]), "r"(a[2]), "r"(a[3]), "r"(b[0]), "r"(b[1]));
}

// =====================================================================
// tf32 warp-MMA GEMM: C[m, n] = sum_k A[m,k] * B[n,k]  (+bias[n])
// Block tile 128x128, BK=32, 256 threads (8 warps, 4x2), warp tile 32x64.
// A/B staged in smem in FRAGMENT-PERMUTED order so consumers do lds.128/lds.64.
//   A frag (m16n8k8 tf32): a0:(r,c) r=lane>>2,c=lane&3; a1:r+8; a2:c+4; a3:both
//   B frag: b0:(k,n) k=lane&3,n=lane>>2; b1:k+4
// smem A layout: [m_tile(8)][k_tile(4)][lane(32)][reg(4)]  -> 4096 u32
// smem B layout: [n_tile(16)][k_tile(4)][lane(32)][reg(2)] -> 4096 u32
// =====================================================================
#define MG_SMEM (2*(4096+4096)*4)   // 65536 bytes

template<bool BIAS>
__global__ __launch_bounds__(256) void mma_gemm(
    const float* __restrict__ A, const float* __restrict__ Bm,
    const float* __restrict__ bias, float* __restrict__ C,
    int M, int Nn, int K, int ldc)
{
    extern __shared__ uint32_t smem[];
    uint32_t* sA = smem;            // 2 x 4096
    uint32_t* sB = smem + 8192;     // 2 x 4096

    int tid = threadIdx.x, lane = tid & 31, wid = tid >> 5;
    int wm = wid & 3, wn = wid >> 2;          // 4 x 2 warp grid
    int tile_m = blockIdx.y * 128, tile_n = blockIdx.x * 128;
    int nch = (K + 31) >> 5;

    float d[2][8][4];
    #pragma unroll
    for (int mi = 0; mi < 2; mi++)
        #pragma unroll
        for (int ni = 0; ni < 8; ni++)
            #pragma unroll
            for (int q = 0; q < 4; q++) d[mi][ni][q] = 0.f;

    float4 stA[4], stB[4];

    // ---- stage chunk `c` globals into registers ----
    auto gload = [&](int c){
        int kbase = c << 5;
        #pragma unroll
        for (int u = 0; u < 4; u++){
            int i = tid + (u << 8);
            int r = i >> 3, c4 = (i & 7) << 2;
            int gm = tile_m + r, gk = kbase + c4;
            float4 v = make_float4(0.f,0.f,0.f,0.f);
            if (gm < M && gk < K) v = *(const float4*)(A + (size_t)gm*K + gk);
            stA[u] = v;
            int gn = tile_n + r;
            float4 w = make_float4(0.f,0.f,0.f,0.f);
            if (gn < Nn && gk < K) w = *(const float4*)(Bm + (size_t)gn*K + gk);
            stB[u] = w;
        }
    };
    // ---- convert + permuted store into buffer s ----
    auto sstore = [&](int s){
        uint32_t* bA = sA + s*4096;
        uint32_t* bB = sB + s*4096;
        #pragma unroll
        for (int u = 0; u < 4; u++){
            int i = tid + (u << 8);
            int r = i >> 3, c4 = (i & 7) << 2;
            // A: element (r, c4+j)
            {
                int m_tile = r >> 4, rr = r & 15;
                int k_tile = c4 >> 3, cc = c4 & 7;         // cc in {0,4}
                int reg = (cc ? 2 : 0) + (rr >= 8 ? 1 : 0);
                int lane0 = (rr & 7) << 2;
                uint32_t base = ((m_tile*4 + k_tile)*32 + lane0)*4 + reg;
                bA[base      ] = f2tf32(stA[u].x);
                bA[base +  4 ] = f2tf32(stA[u].y);
                bA[base +  8 ] = f2tf32(stA[u].z);
                bA[base + 12 ] = f2tf32(stA[u].w);
            }
            // B: element (n=r, k=c4+j)
            {
                int n_tile = r >> 3, nn = r & 7;
                int k_tile = c4 >> 3, kk = c4 & 7;          // kk in {0,4}
                int reg = kk ? 1 : 0;
                int lane0 = nn << 2;
                uint32_t base = ((n_tile*4 + k_tile)*32 + lane0)*2 + reg;
                bB[base     ] = f2tf32(stB[u].x);
                bB[base + 2 ] = f2tf32(stB[u].y);
                bB[base + 4 ] = f2tf32(stB[u].z);
                bB[base + 6 ] = f2tf32(stB[u].w);
            }
        }
    };

    gload(0); sstore(0);
    __syncthreads();

    for (int c = 0; c < nch; c++){
        int s = c & 1;
        if (c + 1 < nch) gload(c + 1);
        const uint32_t* bA = sA + s*4096;
        const uint32_t* bB = sB + s*4096;
        #pragma unroll
        for (int kt = 0; kt < 4; kt++){
            uint32_t a[2][4], b[8][2];
            #pragma unroll
            for (int mi = 0; mi < 2; mi++)
                *(uint4*)a[mi] = *(const uint4*)&bA[(((wm*2+mi)*4 + kt)*32 + lane)*4];
            #pragma unroll
            for (int ni = 0; ni < 8; ni++)
                *(uint2*)b[ni] = *(const uint2*)&bB[(((wn*8+ni)*4 + kt)*32 + lane)*2];
            #pragma unroll
            for (int mi = 0; mi < 2; mi++)
                #pragma unroll
                for (int ni = 0; ni < 8; ni++)
                    mma_tf32(d[mi][ni], a[mi], b[ni]);
        }
        if (c + 1 < nch) sstore((c + 1) & 1);
        __syncthreads();
    }

    // ---- epilogue ----
    int grp = lane >> 2, qid = lane & 3;
    #pragma unroll
    for (int mi = 0; mi < 2; mi++){
        int row0 = tile_m + wm*32 + mi*16 + grp;
        #pragma unroll
        for (int ni = 0; ni < 8; ni++){
            int col = tile_n + wn*64 + ni*8 + qid*2;
            if (col < Nn){
                float b0 = 0.f, b1 = 0.f;
                if (BIAS){ b0 = bias[col]; b1 = bias[col+1]; }
                if (row0 < M){
                    float2 v = make_float2(d[mi][ni][0] + b0, d[mi][ni][1] + b1);
                    *(float2*)(C + (size_t)row0*ldc + col) = v;
                }
                if (row0 + 8 < M){
                    float2 v = make_float2(d[mi][ni][2] + b0, d[mi][ni][3] + b1);
                    *(float2*)(C + (size_t)(row0+8)*ldc + col) = v;
                }
            }
        }
    }
}

// ---------------- K1: gather decoder inputs ----------------
__global__ void k_decin(const float* __restrict__ emb, const float* __restrict__ slot_emb,
                        const int* __restrict__ dom, const int* __restrict__ slo,
                        const int* __restrict__ tgt){
    int idx = blockIdx.x * blockDim.x + threadIdx.x;
    if (idx >= LL*NN*HH) return;
    int h = idx % HH; int r = idx / HH; int n = r % NN; int l = r / NN;
    int s = n / BB, b = n % BB;
    float v;
    if (l == 0) v = slot_emb[dom[s]*HH + h] + slot_emb[slo[s]*HH + h];
    else {
        int tok = tgt[(b*NSLOT + s)*LL + (l-1)];
        v = emb[(size_t)tok*HH + h];
    }
    g_dec_in[idx] = v;
}

// ---------------- K2: init hidden ----------------
__global__ void k_hinit(const float* __restrict__ enc_hidden){
    int idx = blockIdx.x * blockDim.x + threadIdx.x;
    if (idx >= NN*HH) return;
    int n = idx / HH, h = idx % HH;
    g_hprev[idx] = enc_hidden[(n % BB)*HH + h];
}

// ---------------- K3: GRU gate fuse ----------------
__global__ void k_gate(int l){
    int idx = blockIdx.x * blockDim.x + threadIdx.x;
    if (idx >= NN*HH) return;
    int n = idx / HH, k = idx % HH;
    const float* gi = g_gi + (size_t)(l*NN + n)*H3;
    const float* gh = g_gh + (size_t)n*H3;
    float r  = sigmoidf(gi[k]        + gh[k]);
    float z  = sigmoidf(gi[HH + k]   + gh[HH + k]);
    float nn = tanhf   (gi[2*HH + k] + r * gh[2*HH + k]);
    float hp = g_hprev[idx];
    float hn = (1.f - z) * nn + z * hp;
    g_h[(size_t)(l*NN + n)*HH + k] = hn;
    g_hprev[idx] = hn;
}

// ---------------- K4: attention ----------------
#define ENC_PAD 68
__global__ __launch_bounds__(256) void k_attn(const float* __restrict__ enc_out,
                                              const int* __restrict__ lens){
    extern __shared__ float sm[];
    float* sh_h   = sm;
    float* sh_enc = sm + NSLOT*HH;
    float* sh_sc  = sh_enc + TT*ENC_PAD;
    __shared__ float red[8];
    __shared__ float s_mx, s_sum;

    int l  = blockIdx.x / BB;
    int bb = blockIdx.x % BB;
    int tid = threadIdx.x;
    int lane = tid & 31, wrp = tid >> 5;
    int t = tid;

    for (int i = tid; i < NSLOT*HH; i += 256){
        int s = i / HH, h = i % HH;
        sh_h[i] = g_h[(size_t)(l*NN + s*BB + bb)*HH + h];
    }
    for (int i = tid; i < NSLOT*TT; i += 256) sh_sc[i] = 0.f;
    __syncthreads();

    for (int kc = 0; kc < HH; kc += 64){
        int kw = min(64, HH - kc);
        for (int i = tid; i < TT*kw; i += 256){
            int tt2 = i / kw, kk = i % kw;
            sh_enc[tt2*ENC_PAD + kk] = enc_out[((size_t)bb*TT + tt2)*HH + kc + kk];
        }
        __syncthreads();
        for (int sg = 0; sg < NSLOT; sg += 10){
            float acc[10];
            #pragma unroll
            for (int u = 0; u < 10; u++) acc[u] = 0.f;
            for (int kk = 0; kk < kw; kk += 4){
                float4 e = *(const float4*)&sh_enc[t*ENC_PAD + kk];
                #pragma unroll
                for (int u = 0; u < 10; u++){
                    float4 hv = *(const float4*)&sh_h[(sg+u)*HH + kc + kk];
                    acc[u] += hv.x*e.x + hv.y*e.y + hv.z*e.z + hv.w*e.w;
                }
            }
            #pragma unroll
            for (int u = 0; u < 10; u++) sh_sc[(sg+u)*TT + t] += acc[u];
        }
        __syncthreads();
    }

    int len = lens[bb];
    for (int s = 0; s < NSLOT; s++){
        float v = (t < len) ? sh_sc[s*TT + t] : -1e9f;
        float m = warpMax(v);
        if (lane == 0) red[wrp] = m;
        __syncthreads();
        if (tid == 0){
            float mm = red[0];
            #pragma unroll
            for (int i = 1; i < 8; i++) mm = fmaxf(mm, red[i]);
            s_mx = mm;
        }
        __syncthreads();
        float p = expf(v - s_mx);
        float su = warpSum(p);
        if (lane == 0) red[wrp] = su;
        __syncthreads();
        if (tid == 0){
            float ss = 0.f;
            #pragma unroll
            for (int i = 0; i < 8; i++) ss += red[i];
            s_sum = ss;
        }
        __syncthreads();
        p /= s_sum;
        sh_sc[s*TT + t] = p;
        g_prob[(size_t)(l*NN + s*BB + bb)*TT + t] = p;
        __syncthreads();
    }

    for (int hc = 0; hc < HH; hc += 64){
        int hw = min(64, HH - hc);
        __syncthreads();
        for (int i = tid; i < TT*hw; i += 256){
            int tt2 = i / hw, hh = i % hw;
            sh_enc[tt2*ENC_PAD + hh] = enc_out[((size_t)bb*TT + tt2)*HH + hc + hh];
        }
        __syncthreads();
        int nq = NSLOT * (hw >> 2);
        for (int oi = tid; oi < nq; oi += 256){
            int s  = oi / (hw >> 2);
            int h4 = (oi % (hw >> 2)) * 4;
            float4 a = make_float4(0,0,0,0);
            for (int tt2 = 0; tt2 < TT; tt2++){
                float p = sh_sc[s*TT + tt2];
                float4 e = *(const float4*)&sh_enc[tt2*ENC_PAD + h4];
                a.x += p*e.x; a.y += p*e.y; a.z += p*e.z; a.w += p*e.w;
            }
            *(float4*)&g_ctx[(size_t)(l*NN + s*BB + bb)*HH + hc + h4] = a;
        }
    }
}

// ---------------- K5: switch ----------------
__global__ void k_switch(const float* __restrict__ w_ratio, const float* __restrict__ b_ratio){
    int row = blockIdx.x;
    int tid = threadIdx.x;
    const float* h = g_h      + (size_t)row*HH;
    const float* c = g_ctx    + (size_t)row*HH;
    const float* x = g_dec_in + (size_t)row*HH;
    float a = 0.f;
    for (int i = tid; i < HH; i += 128)
        a += h[i]*w_ratio[i] + c[i]*w_ratio[HH + i] + x[i]*w_ratio[2*HH + i];
    __shared__ float red[4];
    a = warpSum(a);
    if ((tid & 31) == 0) red[tid >> 5] = a;
    __syncthreads();
    if (tid == 0){
        float tot = red[0] + red[1] + red[2] + red[3] + b_ratio[0];
        g_switch[row] = sigmoidf(tot);
    }
}

// ---------------- K6: gates head ----------------
__global__ void k_gates(const float* __restrict__ w_gate, const float* __restrict__ b_gate,
                        float* __restrict__ out_gates){
    int n = blockIdx.x;
    int tid = threadIdx.x;
    const float* c = g_ctx + (size_t)n*HH;
    float a0 = 0.f, a1 = 0.f, a2 = 0.f;
    for (int i = tid; i < HH; i += 128){
        float cv = c[i];
        a0 += cv * w_gate[i];
        a1 += cv * w_gate[HH + i];
        a2 += cv * w_gate[2*HH + i];
    }
    __shared__ float red[3][4];
    a0 = warpSum(a0); a1 = warpSum(a1); a2 = warpSum(a2);
    if ((tid & 31) == 0){
        int w = tid >> 5;
        red[0][w] = a0; red[1][w] = a1; red[2][w] = a2;
    }
    __syncthreads();
    if (tid < GG){
        float tot = red[tid][0] + red[tid][1] + red[tid][2] + red[tid][3] + b_gate[tid];
        out_gates[(size_t)n*GG + tid] = tot;
    }
}

// ---------------- K7: rearrange h -> output-row order ----------------
__global__ void k_rearr(){
    int idx = blockIdx.x * blockDim.x + threadIdx.x;
    if (idx >= MM*HH) return;
    int k = idx % HH; int m = idx / HH;
    int n = m / LL, l = m % LL;
    g_Abig[idx] = g_h[(size_t)(l*NN + n)*HH + k];
}

// ---------------- K8: softmax + pointer scatter + mix ----------------
__global__ __launch_bounds__(256) void k_softmix(float* __restrict__ out,
                                                 const int* __restrict__ story){
    extern __shared__ float pctx[];
    __shared__ float red[8];
    __shared__ float s_mx, s_sum;
    int m = blockIdx.x, tid = threadIdx.x;
    int lane = tid & 31, wrp = tid >> 5;
    int n = m / LL, l = m % LL, bb = n % BB;
    int rowa = l*NN + n;
    float sw = g_switch[rowa];

    for (int i = tid; i < VV; i += 256) pctx[i] = 0.f;
    __syncthreads();
    {
        float p = g_prob[(size_t)rowa*TT + tid];
        int c = story[bb*TT + tid];
        atomicAdd(&pctx[c], p);
    }
    __syncthreads();

    float* base = out + (size_t)m*VV;
    float lm = -INFINITY;
    for (int v = tid; v < VV; v += 256) lm = fmaxf(lm, base[v]);
    lm = warpMax(lm);
    if (lane == 0) red[wrp] = lm;
    __syncthreads();
    if (tid == 0){
        float mm = red[0];
        #pragma unroll
        for (int i = 1; i < 8; i++) mm = fmaxf(mm, red[i]);
        s_mx = mm;
    }
    __syncthreads();
    float mx = s_mx;
    float ls = 0.f;
    for (int v = tid; v < VV; v += 256) ls += expf(base[v] - mx);
    ls = warpSum(ls);
    if (lane == 0) red[wrp] = ls;
    __syncthreads();
    if (tid == 0){
        float ss = 0.f;
        #pragma unroll
        for (int i = 0; i < 8; i++) ss += red[i];
        s_sum = ss;
    }
    __syncthreads();
    float scale = sw / s_sum;
    float osw = 1.f - sw;
    for (int v = tid; v < VV; v += 256)
        base[v] = expf(base[v] - mx) * scale + osw * pctx[v];
}

// ---------------- launch ----------------
extern "C" void kernel_launch(void* const* d_in, const int* in_sizes, int n_in,
                              void* d_out, int out_size){
    const float* enc_hidden = (const float*)d_in[0];
    const float* enc_out    = (const float*)d_in[1];
    const float* emb        = (const float*)d_in[2];
    const float* w_ih       = (const float*)d_in[3];
    const float* w_hh       = (const float*)d_in[4];
    const float* b_ih       = (const float*)d_in[5];
    const float* b_hh       = (const float*)d_in[6];
    const float* w_ratio    = (const float*)d_in[7];
    const float* b_ratio    = (const float*)d_in[8];
    const float* w_gate     = (const float*)d_in[9];
    const float* b_gate     = (const float*)d_in[10];
    const float* slot_emb   = (const float*)d_in[11];
    const int*   lens       = (const int*)d_in[12];
    const int*   story      = (const int*)d_in[13];
    const int*   tgt        = (const int*)d_in[14];
    const int*   dom        = (const int*)d_in[15];
    const int*   slo        = (const int*)d_in[16];
    float* out = (float*)d_out;

    float *p_dec, *p_gi, *p_hprev, *p_gh, *p_Abig;
    cudaGetSymbolAddress((void**)&p_dec,   g_dec_in);
    cudaGetSymbolAddress((void**)&p_gi,    g_gi);
    cudaGetSymbolAddress((void**)&p_hprev, g_hprev);
    cudaGetSymbolAddress((void**)&p_gh,    g_gh);
    cudaGetSymbolAddress((void**)&p_Abig,  g_Abig);

    const int ATTN_SMEM = (NSLOT*HH + TT*ENC_PAD + NSLOT*TT) * 4;
    cudaFuncSetAttribute(k_attn, cudaFuncAttributeMaxDynamicSharedMemorySize, ATTN_SMEM);
    cudaFuncSetAttribute(k_softmix, cudaFuncAttributeMaxDynamicSharedMemorySize, VV*4);
    cudaFuncSetAttribute(mma_gemm<true>,  cudaFuncAttributeMaxDynamicSharedMemorySize, MG_SMEM);
    cudaFuncSetAttribute(mma_gemm<false>, cudaFuncAttributeMaxDynamicSharedMemorySize, MG_SMEM);

    // 1) decoder inputs + h0
    k_decin<<<(LL*NN*HH + 255)/256, 256>>>(emb, slot_emb, dom, slo, tgt);
    k_hinit<<<(NN*HH + 255)/256, 256>>>(enc_hidden);

    // 2) input-side gates, all steps: (4800 x 1200 x 400) + b_ih
    {
        dim3 grid((H3 + 127)/128, (MM + 127)/128);
        mma_gemm<true><<<grid, 256, MG_SMEM>>>(p_dec, w_ih, b_ih, p_gi, MM, H3, HH, H3);
    }

    // 3) GRU recurrence
    for (int l = 0; l < LL; l++){
        dim3 grid((H3 + 127)/128, (NN + 127)/128);
        mma_gemm<true><<<grid, 256, MG_SMEM>>>(p_hprev, w_hh, b_hh, p_gh, NN, H3, HH, H3);
        k_gate<<<(NN*HH + 255)/256, 256>>>(l);
    }

    // 4) attention
    k_attn<<<LL*BB, 256, ATTN_SMEM>>>(enc_out, lens);

    // 5) switch; 6) gates head
    k_switch<<<LL*NN, 128>>>(w_ratio, b_ratio);
    k_gates<<<NN, 128>>>(w_gate, b_gate, out + POINTS_ELEMS);

    // 7) big vocab GEMM (tf32 mma.sync), logits straight into d_out
    k_rearr<<<(MM*HH + 255)/256, 256>>>();
    {
        dim3 grid((VV + 127)/128, (MM + 127)/128);
        mma_gemm<false><<<grid, 256, MG_SMEM>>>(p_Abig, emb, nullptr, out, MM, VV, HH, VV);
    }

    // 8) softmax + pointer scatter + mix, in place
    k_softmix<<<MM, 256, VV*4>>>(out, story);
}

// round 4
// speedup vs baseline: 1.5279x; 1.0760x over previous
#include <cuda_runtime.h>
#include <cstdint>
#include <math.h>

// ---------------- problem constants ----------------
#define BB 16
#define TT 256
#define VV 18000
#define NSLOT 30
#define LL 10
#define GG 3
#define HH 400
#define NN (NSLOT*BB)     // 480
#define MM (LL*NN)        // 4800
#define H3 (3*HH)         // 1200
#define NCH 13            // ceil(400/32) K-chunks

// fragment-block counts (rows padded to 128)
#define NBM_BIG 38        // ceil(4800/128)
#define NBM_H   4         // ceil(480/128)
#define NBN_EMB 141       // ceil(18000/128)
#define NBN_W   10        // ceil(1200/128)

static const size_t POINTS_ELEMS = (size_t)MM * VV;

// ---------------- scratch ----------------
__device__ __align__(128) float g_dec_in[LL*NN*HH];
__device__ __align__(128) float g_gi[LL*NN*H3];
__device__ __align__(128) float g_h[LL*NN*HH];
__device__ __align__(128) float g_hprev[NN*HH];
__device__ __align__(128) float g_gh[NN*H3];
__device__ __align__(128) float g_prob[LL*NN*TT];
__device__ __align__(128) float g_ctx[LL*NN*HH];
__device__ __align__(128) float g_switch[LL*NN];

// fragment-permuted tf32 operand buffers
__device__ __align__(128) uint32_t cA_dec[NBM_BIG*NCH*4096];
__device__ __align__(128) uint32_t cA_big[NBM_BIG*NCH*4096];
__device__ __align__(128) uint32_t cA_h  [NBM_H  *NCH*4096];
__device__ __align__(128) uint32_t cB_emb[NBN_EMB*NCH*4096];
__device__ __align__(128) uint32_t cB_wih[NBN_W  *NCH*4096];
__device__ __align__(128) uint32_t cB_whh[NBN_W  *NCH*4096];

// ---------------- helpers ----------------
__device__ __forceinline__ float warpMax(float v){
    #pragma unroll
    for (int o = 16; o; o >>= 1) v = fmaxf(v, __shfl_xor_sync(0xffffffffu, v, o));
    return v;
}
__device__ __forceinline__ float warpSum(float v){
    #pragma unroll
    for (int o = 16; o; o >>= 1) v += __shfl_xor_sync(0xffffffffu, v, o);
    return v;
}
__device__ __forceinline__ float sigmoidf(float x){ return 1.f / (1.f + expf(-x)); }
__device__ __forceinline__ uint32_t f2tf32(float x){
    uint32_t r;
    asm("cvt.rna.tf32.f32 %0, %1;" : "=r"(r) : "f"(x));
    return r;
}
__device__ __forceinline__ void mma_tf32(float* d, const uint32_t* a, const uint32_t* b){
    asm volatile(
        "mma.sync.aligned.m16n8k8.row.col.f32.tf32.tf32.f32 "
        "{%0,%1,%2,%3}, {%4,%5,%6,%7}, {%8,%9}, {%0,%1,%2,%3};\n"
        : "+f"(d[0]), "+f"(d[1]), "+f"(d[2]), "+f"(d[3])
        : "r"(a[0]), "r"(a[1]), "r"(a[2]), "r"(a[3]), "r"(b[0]), "r"(b[1]));
}
__device__ __forceinline__ uint32_t smem_u32(const void* p){
    uint32_t a;
    asm("{ .reg .u64 t; cvta.to.shared.u64 t, %1; cvt.u32.u64 %0, t; }" : "=r"(a) : "l"(p));
    return a;
}
__device__ __forceinline__ void cp16(uint32_t saddr, const void* g){
    asm volatile("cp.async.ca.shared.global [%0], [%1], 16;" :: "r"(saddr), "l"(g) : "memory");
}
__device__ __forceinline__ void cp_commit(){ asm volatile("cp.async.commit_group;" ::: "memory"); }
template<int W> __device__ __forceinline__ void cp_wait(){
    asm volatile("cp.async.wait_group %0;" :: "n"(W) : "memory");
}

// =====================================================================
// conversion kernels: fp32 (row-major RxK) -> fragment-permuted tf32
// A layout per (blk, chunk): [m_tile(8)][k_tile(4)][lane(32)][reg(4)] = 4096 u32 (16KB)
// B layout per (blk, chunk): [n_tile(16)][k_tile(4)][lane(32)][reg(2)] = 4096 u32
// =====================================================================
// REMAP=0: src row r directly. REMAP=1: big-A order, r=m -> g_h row (m%LL)*NN + m/LL
template<int REMAP>
__global__ void conv_A(const float* __restrict__ src, uint32_t* __restrict__ dst,
                       int R, int RP){
    int idx = blockIdx.x * blockDim.x + threadIdx.x;
    const int nq = NCH*8;                 // 104 quads per row
    if (idx >= RP*nq) return;
    int r = idx / nq, q = idx % nq;
    int k = q << 2;
    float4 v = make_float4(0.f,0.f,0.f,0.f);
    if (r < R && k < HH){
        if (REMAP){
            int n = r / LL, l = r % LL;
            v = *(const float4*)(g_h + (size_t)(l*NN + n)*HH + k);
        } else {
            v = *(const float4*)(src + (size_t)r*HH + k);
        }
    }
    int blk = r >> 7, rl = r & 127;
    int m_tile = rl >> 4, rr = rl & 15;
    int c = k >> 5, kin = k & 31;
    int k_tile = kin >> 3, cc = kin & 7;
    int reg = (cc ? 2 : 0) + (rr >= 8 ? 1 : 0);
    int lane0 = (rr & 7) << 2;
    size_t base = (size_t)(blk*NCH + c)*4096 + ((m_tile*4 + k_tile)*32 + lane0)*4 + reg;
    dst[base     ] = f2tf32(v.x);
    dst[base +  4] = f2tf32(v.y);
    dst[base +  8] = f2tf32(v.z);
    dst[base + 12] = f2tf32(v.w);
}

__global__ void conv_B(const float* __restrict__ src, uint32_t* __restrict__ dst,
                       int R, int RP){
    int idx = blockIdx.x * blockDim.x + threadIdx.x;
    const int nq = NCH*8;
    if (idx >= RP*nq) return;
    int r = idx / nq, q = idx % nq;
    int k = q << 2;
    float4 v = make_float4(0.f,0.f,0.f,0.f);
    if (r < R && k < HH) v = *(const float4*)(src + (size_t)r*HH + k);
    int blk = r >> 7, rl = r & 127;
    int n_tile = rl >> 3, nn = rl & 7;
    int c = k >> 5, kin = k & 31;
    int k_tile = kin >> 3, cc = kin & 7;
    int reg = (cc >= 4) ? 1 : 0;
    int lane0 = nn << 2;
    size_t base = (size_t)(blk*NCH + c)*4096 + ((n_tile*4 + k_tile)*32 + lane0)*2 + reg;
    dst[base    ] = f2tf32(v.x);
    dst[base + 2] = f2tf32(v.y);
    dst[base + 4] = f2tf32(v.z);
    dst[base + 6] = f2tf32(v.w);
}

// =====================================================================
// tf32 MMA GEMM v2: pre-permuted operands, cp.async double-buffered.
// C[m,n] = sum_k A[m,k]*B[n,k] (+bias). Block 128x128, 8 warps 4x2.
// =====================================================================
#define MG_SMEM 65536   // 2 x (16KB A + 16KB B)

template<bool BIAS>
__global__ __launch_bounds__(256) void mma_gemm2(
    const uint32_t* __restrict__ Af, const uint32_t* __restrict__ Bf,
    const float* __restrict__ bias, float* __restrict__ C,
    int M, int Nn, int ldc)
{
    extern __shared__ uint32_t sm2[];
    uint32_t sbase = smem_u32(sm2);
    int tid = threadIdx.x, lane = tid & 31, wid = tid >> 5;
    int wm = wid & 3, wn = wid >> 2;
    const uint32_t* gA = Af + (size_t)blockIdx.y * NCH * 4096;
    const uint32_t* gB = Bf + (size_t)blockIdx.x * NCH * 4096;

    float d[2][8][4];
    #pragma unroll
    for (int mi = 0; mi < 2; mi++)
        #pragma unroll
        for (int ni = 0; ni < 8; ni++)
            #pragma unroll
            for (int q = 0; q < 4; q++) d[mi][ni][q] = 0.f;

    auto pre = [&](int c){
        int s = c & 1;
        uint32_t sA = sbase + s*16384u;
        uint32_t sB = sbase + 32768u + s*16384u;
        const uint32_t* a = gA + c*4096;
        const uint32_t* b = gB + c*4096;
        #pragma unroll
        for (int u = 0; u < 4; u++){
            int off = (tid + (u << 8)) << 2;           // u32 index
            cp16(sA + (off << 2), a + off);
            cp16(sB + (off << 2), b + off);
        }
        cp_commit();
    };

    pre(0);
    for (int c = 0; c < NCH; c++){
        if (c + 1 < NCH){ pre(c + 1); cp_wait<1>(); }
        else cp_wait<0>();
        __syncthreads();
        const uint32_t* bA = sm2 + (c & 1)*4096;
        const uint32_t* bB = sm2 + 8192 + (c & 1)*4096;
        #pragma unroll
        for (int kt = 0; kt < 4; kt++){
            uint32_t a[2][4], b[8][2];
            #pragma unroll
            for (int mi = 0; mi < 2; mi++)
                *(uint4*)a[mi] = *(const uint4*)&bA[(((wm*2+mi)*4 + kt)*32 + lane)*4];
            #pragma unroll
            for (int ni = 0; ni < 8; ni++)
                *(uint2*)b[ni] = *(const uint2*)&bB[(((wn*8+ni)*4 + kt)*32 + lane)*2];
            #pragma unroll
            for (int mi = 0; mi < 2; mi++)
                #pragma unroll
                for (int ni = 0; ni < 8; ni++)
                    mma_tf32(d[mi][ni], a[mi], b[ni]);
        }
        __syncthreads();
    }

    int grp = lane >> 2, qid = lane & 3;
    int tile_m = blockIdx.y * 128, tile_n = blockIdx.x * 128;
    #pragma unroll
    for (int mi = 0; mi < 2; mi++){
        int row0 = tile_m + wm*32 + mi*16 + grp;
        #pragma unroll
        for (int ni = 0; ni < 8; ni++){
            int col = tile_n + wn*64 + ni*8 + qid*2;
            if (col < Nn){
                float b0 = 0.f, b1 = 0.f;
                if (BIAS){ b0 = bias[col]; b1 = bias[col+1]; }
                if (row0 < M){
                    float2 v = make_float2(d[mi][ni][0] + b0, d[mi][ni][1] + b1);
                    *(float2*)(C + (size_t)row0*ldc + col) = v;
                }
                if (row0 + 8 < M){
                    float2 v = make_float2(d[mi][ni][2] + b0, d[mi][ni][3] + b1);
                    *(float2*)(C + (size_t)(row0+8)*ldc + col) = v;
                }
            }
        }
    }
}

// ---------------- K1: gather decoder inputs ----------------
__global__ void k_decin(const float* __restrict__ emb, const float* __restrict__ slot_emb,
                        const int* __restrict__ dom, const int* __restrict__ slo,
                        const int* __restrict__ tgt){
    int idx = blockIdx.x * blockDim.x + threadIdx.x;
    if (idx >= LL*NN*HH) return;
    int h = idx % HH; int r = idx / HH; int n = r % NN; int l = r / NN;
    int s = n / BB, b = n % BB;
    float v;
    if (l == 0) v = slot_emb[dom[s]*HH + h] + slot_emb[slo[s]*HH + h];
    else {
        int tok = tgt[(b*NSLOT + s)*LL + (l-1)];
        v = emb[(size_t)tok*HH + h];
    }
    g_dec_in[idx] = v;
}

// ---------------- K2: init hidden ----------------
__global__ void k_hinit(const float* __restrict__ enc_hidden){
    int idx = blockIdx.x * blockDim.x + threadIdx.x;
    if (idx >= NN*HH) return;
    int n = idx / HH, h = idx % HH;
    g_hprev[idx] = enc_hidden[(n % BB)*HH + h];
}

// ---------------- K3: GRU gate fuse ----------------
__global__ void k_gate(int l){
    int idx = blockIdx.x * blockDim.x + threadIdx.x;
    if (idx >= NN*HH) return;
    int n = idx / HH, k = idx % HH;
    const float* gi = g_gi + (size_t)(l*NN + n)*H3;
    const float* gh = g_gh + (size_t)n*H3;
    float r  = sigmoidf(gi[k]        + gh[k]);
    float z  = sigmoidf(gi[HH + k]   + gh[HH + k]);
    float nn = tanhf   (gi[2*HH + k] + r * gh[2*HH + k]);
    float hp = g_hprev[idx];
    float hn = (1.f - z) * nn + z * hp;
    g_h[(size_t)(l*NN + n)*HH + k] = hn;
    g_hprev[idx] = hn;
}

// ---------------- K4: attention ----------------
#define ENC_PAD 68
__global__ __launch_bounds__(256) void k_attn(const float* __restrict__ enc_out,
                                              const int* __restrict__ lens){
    extern __shared__ float sm[];
    float* sh_h   = sm;
    float* sh_enc = sm + NSLOT*HH;
    float* sh_sc  = sh_enc + TT*ENC_PAD;
    __shared__ float red[8];
    __shared__ float s_mx, s_sum;

    int l  = blockIdx.x / BB;
    int bb = blockIdx.x % BB;
    int tid = threadIdx.x;
    int lane = tid & 31, wrp = tid >> 5;
    int t = tid;

    for (int i = tid; i < NSLOT*HH; i += 256){
        int s = i / HH, h = i % HH;
        sh_h[i] = g_h[(size_t)(l*NN + s*BB + bb)*HH + h];
    }
    for (int i = tid; i < NSLOT*TT; i += 256) sh_sc[i] = 0.f;
    __syncthreads();

    for (int kc = 0; kc < HH; kc += 64){
        int kw = min(64, HH - kc);
        for (int i = tid; i < TT*kw; i += 256){
            int tt2 = i / kw, kk = i % kw;
            sh_enc[tt2*ENC_PAD + kk] = enc_out[((size_t)bb*TT + tt2)*HH + kc + kk];
        }
        __syncthreads();
        for (int sg = 0; sg < NSLOT; sg += 10){
            float acc[10];
            #pragma unroll
            for (int u = 0; u < 10; u++) acc[u] = 0.f;
            for (int kk = 0; kk < kw; kk += 4){
                float4 e = *(const float4*)&sh_enc[t*ENC_PAD + kk];
                #pragma unroll
                for (int u = 0; u < 10; u++){
                    float4 hv = *(const float4*)&sh_h[(sg+u)*HH + kc + kk];
                    acc[u] += hv.x*e.x + hv.y*e.y + hv.z*e.z + hv.w*e.w;
                }
            }
            #pragma unroll
            for (int u = 0; u < 10; u++) sh_sc[(sg+u)*TT + t] += acc[u];
        }
        __syncthreads();
    }

    int len = lens[bb];
    for (int s = 0; s < NSLOT; s++){
        float v = (t < len) ? sh_sc[s*TT + t] : -1e9f;
        float m = warpMax(v);
        if (lane == 0) red[wrp] = m;
        __syncthreads();
        if (tid == 0){
            float mm = red[0];
            #pragma unroll
            for (int i = 1; i < 8; i++) mm = fmaxf(mm, red[i]);
            s_mx = mm;
        }
        __syncthreads();
        float p = expf(v - s_mx);
        float su = warpSum(p);
        if (lane == 0) red[wrp] = su;
        __syncthreads();
        if (tid == 0){
            float ss = 0.f;
            #pragma unroll
            for (int i = 0; i < 8; i++) ss += red[i];
            s_sum = ss;
        }
        __syncthreads();
        p /= s_sum;
        sh_sc[s*TT + t] = p;
        g_prob[(size_t)(l*NN + s*BB + bb)*TT + t] = p;
        __syncthreads();
    }

    for (int hc = 0; hc < HH; hc += 64){
        int hw = min(64, HH - hc);
        __syncthreads();
        for (int i = tid; i < TT*hw; i += 256){
            int tt2 = i / hw, hh = i % hw;
            sh_enc[tt2*ENC_PAD + hh] = enc_out[((size_t)bb*TT + tt2)*HH + hc + hh];
        }
        __syncthreads();
        int nq = NSLOT * (hw >> 2);
        for (int oi = tid; oi < nq; oi += 256){
            int s  = oi / (hw >> 2);
            int h4 = (oi % (hw >> 2)) * 4;
            float4 a = make_float4(0,0,0,0);
            for (int tt2 = 0; tt2 < TT; tt2++){
                float p = sh_sc[s*TT + tt2];
                float4 e = *(const float4*)&sh_enc[tt2*ENC_PAD + h4];
                a.x += p*e.x; a.y += p*e.y; a.z += p*e.z; a.w += p*e.w;
            }
            *(float4*)&g_ctx[(size_t)(l*NN + s*BB + bb)*HH + hc + h4] = a;
        }
    }
}

// ---------------- K5: switch ----------------
__global__ void k_switch(const float* __restrict__ w_ratio, const float* __restrict__ b_ratio){
    int row = blockIdx.x;
    int tid = threadIdx.x;
    const float* h = g_h      + (size_t)row*HH;
    const float* c = g_ctx    + (size_t)row*HH;
    const float* x = g_dec_in + (size_t)row*HH;
    float a = 0.f;
    for (int i = tid; i < HH; i += 128)
        a += h[i]*w_ratio[i] + c[i]*w_ratio[HH + i] + x[i]*w_ratio[2*HH + i];
    __shared__ float red[4];
    a = warpSum(a);
    if ((tid & 31) == 0) red[tid >> 5] = a;
    __syncthreads();
    if (tid == 0){
        float tot = red[0] + red[1] + red[2] + red[3] + b_ratio[0];
        g_switch[row] = sigmoidf(tot);
    }
}

// ---------------- K6: gates head ----------------
__global__ void k_gates(const float* __restrict__ w_gate, const float* __restrict__ b_gate,
                        float* __restrict__ out_gates){
    int n = blockIdx.x;
    int tid = threadIdx.x;
    const float* c = g_ctx + (size_t)n*HH;
    float a0 = 0.f, a1 = 0.f, a2 = 0.f;
    for (int i = tid; i < HH; i += 128){
        float cv = c[i];
        a0 += cv * w_gate[i];
        a1 += cv * w_gate[HH + i];
        a2 += cv * w_gate[2*HH + i];
    }
    __shared__ float red[3][4];
    a0 = warpSum(a0); a1 = warpSum(a1); a2 = warpSum(a2);
    if ((tid & 31) == 0){
        int w = tid >> 5;
        red[0][w] = a0; red[1][w] = a1; red[2][w] = a2;
    }
    __syncthreads();
    if (tid < GG){
        float tot = red[tid][0] + red[tid][1] + red[tid][2] + red[tid][3] + b_gate[tid];
        out_gates[(size_t)n*GG + tid] = tot;
    }
}

// ---------------- K8: softmax + pointer scatter + mix (single gmem pass) ------
__global__ __launch_bounds__(256) void k_softmix(float* __restrict__ out,
                                                 const int* __restrict__ story){
    extern __shared__ float smx[];
    float* pctx = smx;            // VV floats
    float* vals = smx + VV;       // VV floats
    __shared__ float red[8];
    __shared__ float s_mx, s_sum;
    int m = blockIdx.x, tid = threadIdx.x;
    int lane = tid & 31, wrp = tid >> 5;
    int n = m / LL, l = m % LL, bb = n % BB;
    int rowa = l*NN + n;
    float sw = g_switch[rowa];

    for (int i = tid; i < VV; i += 256) pctx[i] = 0.f;
    float* base = out + (size_t)m*VV;
    float lm = -INFINITY;
    for (int v = tid; v < VV; v += 256){
        float x = base[v];
        vals[v] = x;
        lm = fmaxf(lm, x);
    }
    __syncthreads();
    {
        float p = g_prob[(size_t)rowa*TT + tid];
        int c = story[bb*TT + tid];
        atomicAdd(&pctx[c], p);
    }
    lm = warpMax(lm);
    if (lane == 0) red[wrp] = lm;
    __syncthreads();
    if (tid == 0){
        float mm = red[0];
        #pragma unroll
        for (int i = 1; i < 8; i++) mm = fmaxf(mm, red[i]);
        s_mx = mm;
    }
    __syncthreads();
    float mx = s_mx;
    float ls = 0.f;
    for (int v = tid; v < VV; v += 256){
        float e = expf(vals[v] - mx);
        vals[v] = e;
        ls += e;
    }
    ls = warpSum(ls);
    if (lane == 0) red[wrp] = ls;
    __syncthreads();
    if (tid == 0){
        float ss = 0.f;
        #pragma unroll
        for (int i = 0; i < 8; i++) ss += red[i];
        s_sum = ss;
    }
    __syncthreads();
    float scale = sw / s_sum;
    float osw = 1.f - sw;
    for (int v = tid; v < VV; v += 256)
        base[v] = vals[v] * scale + osw * pctx[v];
}

// ---------------- launch ----------------
extern "C" void kernel_launch(void* const* d_in, const int* in_sizes, int n_in,
                              void* d_out, int out_size){
    const float* enc_hidden = (const float*)d_in[0];
    const float* enc_out    = (const float*)d_in[1];
    const float* emb        = (const float*)d_in[2];
    const float* w_ih       = (const float*)d_in[3];
    const float* w_hh       = (const float*)d_in[4];
    const float* b_ih       = (const float*)d_in[5];
    const float* b_hh       = (const float*)d_in[6];
    const float* w_ratio    = (const float*)d_in[7];
    const float* b_ratio    = (const float*)d_in[8];
    const float* w_gate     = (const float*)d_in[9];
    const float* b_gate     = (const float*)d_in[10];
    const float* slot_emb   = (const float*)d_in[11];
    const int*   lens       = (const int*)d_in[12];
    const int*   story      = (const int*)d_in[13];
    const int*   tgt        = (const int*)d_in[14];
    const int*   dom        = (const int*)d_in[15];
    const int*   slo        = (const int*)d_in[16];
    float* out = (float*)d_out;

    float *p_dec, *p_gi, *p_hprev, *p_gh;
    uint32_t *pA_dec, *pA_big, *pA_h, *pB_emb, *pB_wih, *pB_whh;
    cudaGetSymbolAddress((void**)&p_dec,   g_dec_in);
    cudaGetSymbolAddress((void**)&p_gi,    g_gi);
    cudaGetSymbolAddress((void**)&p_hprev, g_hprev);
    cudaGetSymbolAddress((void**)&p_gh,    g_gh);
    cudaGetSymbolAddress((void**)&pA_dec,  cA_dec);
    cudaGetSymbolAddress((void**)&pA_big,  cA_big);
    cudaGetSymbolAddress((void**)&pA_h,    cA_h);
    cudaGetSymbolAddress((void**)&pB_emb,  cB_emb);
    cudaGetSymbolAddress((void**)&pB_wih,  cB_wih);
    cudaGetSymbolAddress((void**)&pB_whh,  cB_whh);

    const int ATTN_SMEM = (NSLOT*HH + TT*ENC_PAD + NSLOT*TT) * 4;
    const int SMX_SMEM  = 2*VV*4;   // 144000
    cudaFuncSetAttribute(k_attn, cudaFuncAttributeMaxDynamicSharedMemorySize, ATTN_SMEM);
    cudaFuncSetAttribute(k_softmix, cudaFuncAttributeMaxDynamicSharedMemorySize, SMX_SMEM);
    cudaFuncSetAttribute(mma_gemm2<true>,  cudaFuncAttributeMaxDynamicSharedMemorySize, MG_SMEM);
    cudaFuncSetAttribute(mma_gemm2<false>, cudaFuncAttributeMaxDynamicSharedMemorySize, MG_SMEM);

    const int nq = NCH*8;

    // 0) weight conversions (emb / w_ih / w_hh) — independent of GRU chain
    conv_B<<<(NBN_EMB*128*nq + 255)/256, 256>>>(emb,  pB_emb, VV,  NBN_EMB*128);
    conv_B<<<(NBN_W  *128*nq + 255)/256, 256>>>(w_ih, pB_wih, H3,  NBN_W*128);
    conv_B<<<(NBN_W  *128*nq + 255)/256, 256>>>(w_hh, pB_whh, H3,  NBN_W*128);

    // 1) decoder inputs + h0
    k_decin<<<(LL*NN*HH + 255)/256, 256>>>(emb, slot_emb, dom, slo, tgt);
    k_hinit<<<(NN*HH + 255)/256, 256>>>(enc_hidden);

    // 2) input-side gates, all steps: (4800 x 1200 x 400) + b_ih
    conv_A<0><<<(NBM_BIG*128*nq + 255)/256, 256>>>(p_dec, pA_dec, MM, NBM_BIG*128);
    {
        dim3 grid(NBN_W, NBM_BIG);
        mma_gemm2<true><<<grid, 256, MG_SMEM>>>(pA_dec, pB_wih, b_ih, p_gi, MM, H3, H3);
    }

    // 3) GRU recurrence
    for (int l = 0; l < LL; l++){
        conv_A<0><<<(NBM_H*128*nq + 255)/256, 256>>>(p_hprev, pA_h, NN, NBM_H*128);
        dim3 grid(NBN_W, NBM_H);
        mma_gemm2<true><<<grid, 256, MG_SMEM>>>(pA_h, pB_whh, b_hh, p_gh, NN, H3, H3);
        k_gate<<<(NN*HH + 255)/256, 256>>>(l);
    }

    // 4) attention
    k_attn<<<LL*BB, 256, ATTN_SMEM>>>(enc_out, lens);

    // 5) switch; 6) gates head
    k_switch<<<LL*NN, 128>>>(w_ratio, b_ratio);
    k_gates<<<NN, 128>>>(w_gate, b_gate, out + POINTS_ELEMS);

    // 7) big vocab GEMM (remapped A conversion fused), logits into d_out
    conv_A<1><<<(NBM_BIG*128*nq + 255)/256, 256>>>(nullptr, pA_big, MM, NBM_BIG*128);
    {
        dim3 grid(NBN_EMB, NBM_BIG);
        mma_gemm2<false><<<grid, 256, MG_SMEM>>>(pA_big, pB_emb, nullptr, out, MM, VV, VV);
    }

    // 8) softmax + pointer scatter + mix, in place
    k_softmix<<<MM, 256, SMX_SMEM>>>(out, story);
}